// round 1
// baseline (speedup 1.0000x reference)
#include <cuda_runtime.h>
#include <math.h>

#define BB 2
#define SS 1024
#define DD 1024
#define HH 16
#define HD 64
#define LL 4
#define VV 32000
#define NROW (BB * SS)   // 2048

// ---------------- scratch (static device globals; no allocs allowed) --------
__device__ float g_x[NROW * DD];
__device__ float g_q[NROW * DD];
__device__ float g_k[NROW * DD];
__device__ float g_v[NROW * DD];
__device__ float g_ctx[NROW * DD];
__device__ float g_attn[NROW * DD];

// ---------------- embedding + sinusoidal positional encoding ---------------
__global__ void embed_kernel(const int* __restrict__ tokens,
                             const float* __restrict__ emb,
                             float* __restrict__ x)
{
    int row = blockIdx.x;            // 0..2047  (b*S + s)
    int pos = row & (SS - 1);        // s
    int tok = tokens[row];
    const float* e = emb + (size_t)tok * DD;
    float* xr = x + (size_t)row * DD;
    const float c = -logf(10000.0f) / (float)DD;
    for (int d = threadIdx.x; d < DD; d += blockDim.x) {
        int i = d >> 1;
        float ang = (float)pos * expf((float)(2 * i) * c);
        float pe = (d & 1) ? cosf(ang) : sinf(ang);
        xr[d] = e[d] + pe;
    }
}

// ---------------- GEMM: C[M,N] = A[M,K] @ W[K,N] + bias[N] -----------------
// BM=BN=128, BK=16, 256 threads, 8x8 per-thread microtile.
__global__ void __launch_bounds__(256)
gemm_bias_kernel(const float* __restrict__ A, const float* __restrict__ W,
                 const float* __restrict__ bias, float* __restrict__ C,
                 int M, int N, int K)
{
    __shared__ float As[16][132];   // [k][m], +4 pad keeps 16B alignment & kills conflicts
    __shared__ float Bs[16][128];   // [k][n]

    const int bm = blockIdx.y * 128;
    const int bn = blockIdx.x * 128;
    const int t  = threadIdx.x;          // 0..255
    const int tx = t & 15;               // n-dim
    const int ty = t >> 4;               // m-dim

    float acc[8][8];
#pragma unroll
    for (int i = 0; i < 8; i++)
#pragma unroll
        for (int j = 0; j < 8; j++) acc[i][j] = 0.0f;

    for (int k0 = 0; k0 < K; k0 += 16) {
        // load A tile 128x16 as float4 (512 vec4, 2 per thread), store transposed
#pragma unroll
        for (int i = 0; i < 2; i++) {
            int idx4 = t + i * 256;          // 0..511
            int r  = idx4 >> 2;              // 0..127
            int c4 = idx4 & 3;               // 0..3
            float4 v = *(const float4*)(A + (size_t)(bm + r) * K + k0 + c4 * 4);
            As[c4 * 4 + 0][r] = v.x;
            As[c4 * 4 + 1][r] = v.y;
            As[c4 * 4 + 2][r] = v.z;
            As[c4 * 4 + 3][r] = v.w;
        }
        // load B tile 16x128 as float4
#pragma unroll
        for (int i = 0; i < 2; i++) {
            int idx4 = t + i * 256;          // 0..511
            int r  = idx4 >> 5;              // 0..15
            int c4 = idx4 & 31;              // 0..31
            float4 v = *(const float4*)(W + (size_t)(k0 + r) * N + bn + c4 * 4);
            *(float4*)&Bs[r][c4 * 4] = v;
        }
        __syncthreads();

#pragma unroll
        for (int kk = 0; kk < 16; kk++) {
            float a[8], b[8];
            float4 a0 = *(const float4*)&As[kk][ty * 8];
            float4 a1 = *(const float4*)&As[kk][ty * 8 + 4];
            float4 b0 = *(const float4*)&Bs[kk][tx * 8];
            float4 b1 = *(const float4*)&Bs[kk][tx * 8 + 4];
            a[0]=a0.x; a[1]=a0.y; a[2]=a0.z; a[3]=a0.w;
            a[4]=a1.x; a[5]=a1.y; a[6]=a1.z; a[7]=a1.w;
            b[0]=b0.x; b[1]=b0.y; b[2]=b0.z; b[3]=b0.w;
            b[4]=b1.x; b[5]=b1.y; b[6]=b1.z; b[7]=b1.w;
#pragma unroll
            for (int i = 0; i < 8; i++)
#pragma unroll
                for (int j = 0; j < 8; j++)
                    acc[i][j] += a[i] * b[j];
        }
        __syncthreads();
    }

#pragma unroll
    for (int i = 0; i < 8; i++) {
        int row = bm + ty * 8 + i;
        float* crow = C + (size_t)row * N + bn + tx * 8;
        const float* brow = bias + bn + tx * 8;
#pragma unroll
        for (int j = 0; j < 8; j += 4) {
            float4 bv = *(const float4*)(brow + j);
            float4 o;
            o.x = acc[i][j + 0] + bv.x;
            o.y = acc[i][j + 1] + bv.y;
            o.z = acc[i][j + 2] + bv.z;
            o.w = acc[i][j + 3] + bv.w;
            *(float4*)(crow + j) = o;
        }
    }
}

// ---------------- causal flash attention (per-head, online softmax) --------
// grid: (S/128, H, B); 128 threads; thread = one query row.
__global__ void __launch_bounds__(128)
attn_kernel(const float* __restrict__ Q, const float* __restrict__ K,
            const float* __restrict__ V, float* __restrict__ O)
{
    __shared__ float Ks[32][64];
    __shared__ float Vs[32][64];

    const int b = blockIdx.z;
    const int h = blockIdx.y;
    const int qi = blockIdx.x * 128 + threadIdx.x;     // query index within seq
    const size_t base = (size_t)(b * SS) * DD + (size_t)h * HD;

    float q[64];
    {
        const float* qrow = Q + base + (size_t)qi * DD;
#pragma unroll
        for (int d = 0; d < 64; d += 4) {
            float4 v = *(const float4*)(qrow + d);
            q[d] = v.x; q[d+1] = v.y; q[d+2] = v.z; q[d+3] = v.w;
        }
    }

    float o[64];
#pragma unroll
    for (int d = 0; d < 64; d++) o[d] = 0.0f;
    float m = -1e30f, l = 0.0f;

    const int kend = blockIdx.x * 128 + 128;           // causal upper bound for block
    for (int kt = 0; kt < kend; kt += 32) {
        // cooperative load of 32x64 K and V tiles
#pragma unroll
        for (int i = 0; i < 4; i++) {
            int idx4 = threadIdx.x + i * 128;          // 0..511 (float4 units)
            int r = idx4 >> 4;                         // 0..31
            int c = (idx4 & 15) * 4;                   // 0..60
            size_t g = base + (size_t)(kt + r) * DD + c;
            *(float4*)&Ks[r][c] = *(const float4*)(K + g);
            *(float4*)&Vs[r][c] = *(const float4*)(V + g);
        }
        __syncthreads();

        int jmax = qi - kt + 1;
        if (jmax > 32) jmax = 32;
        for (int j = 0; j < jmax; j++) {
            float s = 0.0f;
#pragma unroll
            for (int d = 0; d < 64; d++) s += q[d] * Ks[j][d];
            s *= 0.125f;                               // 1/sqrt(64)
            float nm = fmaxf(m, s);
            float corr = __expf(m - nm);
            float p = __expf(s - nm);
            l = l * corr + p;
#pragma unroll
            for (int d = 0; d < 64; d++)
                o[d] = o[d] * corr + p * Vs[j][d];
            m = nm;
        }
        __syncthreads();
    }

    float inv = 1.0f / l;
    float* orow = O + base + (size_t)qi * DD;
#pragma unroll
    for (int d = 0; d < 64; d += 4) {
        float4 v;
        v.x = o[d] * inv; v.y = o[d+1] * inv;
        v.z = o[d+2] * inv; v.w = o[d+3] * inv;
        *(float4*)(orow + d) = v;
    }
}

// ---------------- residual add + layernorm (in place on x) ----------------
__global__ void __launch_bounds__(256)
ln_res_kernel(float* __restrict__ x, const float* __restrict__ res,
              const float* __restrict__ g, const float* __restrict__ beta)
{
    __shared__ float red[256];
    const int row = blockIdx.x;
    const int tid = threadIdx.x;
    float* xr = x + (size_t)row * DD;
    const float* rr = res + (size_t)row * DD;

    float y[4];
    float s = 0.0f;
#pragma unroll
    for (int i = 0; i < 4; i++) {
        int d = tid + i * 256;
        y[i] = xr[d] + rr[d];
        s += y[i];
    }
    red[tid] = s; __syncthreads();
    for (int off = 128; off > 0; off >>= 1) {
        if (tid < off) red[tid] += red[tid + off];
        __syncthreads();
    }
    float mu = red[0] * (1.0f / (float)DD);
    __syncthreads();

    float vs = 0.0f;
#pragma unroll
    for (int i = 0; i < 4; i++) {
        float d2 = y[i] - mu;
        vs += d2 * d2;
    }
    red[tid] = vs; __syncthreads();
    for (int off = 128; off > 0; off >>= 1) {
        if (tid < off) red[tid] += red[tid + off];
        __syncthreads();
    }
    float var = red[0] * (1.0f / (float)DD);
    float inv = rsqrtf(var + 1e-5f);

#pragma unroll
    for (int i = 0; i < 4; i++) {
        int d = tid + i * 256;
        xr[d] = (y[i] - mu) * inv * g[d] + beta[d];
    }
}

// ---------------------------------------------------------------------------
extern "C" void kernel_launch(void* const* d_in, const int* in_sizes, int n_in,
                              void* d_out, int out_size)
{
    const int*   tokens = (const int*)  d_in[0];
    const float* emb    = (const float*)d_in[1];
    const float* qw     = (const float*)d_in[2];
    const float* qb     = (const float*)d_in[3];
    const float* kw     = (const float*)d_in[4];
    const float* kb     = (const float*)d_in[5];
    const float* vw     = (const float*)d_in[6];
    const float* vb     = (const float*)d_in[7];
    const float* ow     = (const float*)d_in[8];
    const float* ob     = (const float*)d_in[9];
    const float* ln_g   = (const float*)d_in[10];
    const float* ln_b   = (const float*)d_in[11];
    const float* out_w  = (const float*)d_in[12];
    const float* out_b  = (const float*)d_in[13];
    float* logits = (float*)d_out;

    float *x, *q, *k, *v, *ctx, *attn;
    cudaGetSymbolAddress((void**)&x,    g_x);
    cudaGetSymbolAddress((void**)&q,    g_q);
    cudaGetSymbolAddress((void**)&k,    g_k);
    cudaGetSymbolAddress((void**)&v,    g_v);
    cudaGetSymbolAddress((void**)&ctx,  g_ctx);
    cudaGetSymbolAddress((void**)&attn, g_attn);

    // 1. embedding + positional encoding
    embed_kernel<<<NROW, 256>>>(tokens, emb, x);

    dim3 gproj(DD / 128, NROW / 128);     // (8, 16)
    dim3 gattn(SS / 128, HH, BB);         // (8, 16, 2)

    for (int l = 0; l < LL; l++) {
        size_t wo = (size_t)l * DD * DD;
        size_t bo = (size_t)l * DD;
        gemm_bias_kernel<<<gproj, 256>>>(x, qw + wo, qb + bo, q, NROW, DD, DD);
        gemm_bias_kernel<<<gproj, 256>>>(x, kw + wo, kb + bo, k, NROW, DD, DD);
        gemm_bias_kernel<<<gproj, 256>>>(x, vw + wo, vb + bo, v, NROW, DD, DD);
        attn_kernel<<<gattn, 128>>>(q, k, v, ctx);
        gemm_bias_kernel<<<gproj, 256>>>(ctx, ow + wo, ob + bo, attn, NROW, DD, DD);
        ln_res_kernel<<<NROW, 256>>>(x, attn, ln_g + bo, ln_b + bo);
    }

    // final logits: [2048,1024] @ [1024,32000] + bias
    dim3 gout(VV / 128, NROW / 128);      // (250, 16)
    gemm_bias_kernel<<<gout, 256>>>(x, out_w, out_b, logits, NROW, VV, DD);
}

// round 3
// speedup vs baseline: 1.8918x; 1.8918x over previous
#include <cuda_runtime.h>
#include <cstdint>
#include <math.h>

#define BB 2
#define SS 1024
#define DD 1024
#define HH 16
#define HD 64
#define LL 4
#define VV 32000
#define NROW (BB * SS)   // 2048

// ---------------- scratch (static device globals; no allocs allowed) --------
__device__ float g_x[NROW * DD];
__device__ float g_q[NROW * DD];
__device__ float g_k[NROW * DD];
__device__ float g_v[NROW * DD];
__device__ float g_ctx[NROW * DD];
__device__ float g_attn[NROW * DD];

__device__ __forceinline__ float tf32r(float x) {
    float r; asm("cvt.rna.tf32.f32 %0, %1;" : "=f"(r) : "f"(x)); return r;
}

// =================== tf32 mma.sync GEMM =====================================
// C[M,N] = A[M,K] @ W[K,N] + bias[N]
// CTA tile 128x128, BK=16, 256 threads (8 warps), warp tile 64x32.
// Fragments: m16n8k8 tf32, 4 (M) x 4 (N) per warp per k8 step.
// As[m][k] stride 20 floats, Bs[k][n] stride 136 floats: conflict-free frag reads.

#define AS_STRIDE 20
#define BS_STRIDE 136

__global__ void __launch_bounds__(256)
gemm_mma(const float* __restrict__ A, const float* __restrict__ W,
         const float* __restrict__ bias, float* __restrict__ C,
         int M, int N, int K)
{
    __shared__ float As[2][128 * AS_STRIDE];   // 2 x 10240 B
    __shared__ float Bs[2][16 * BS_STRIDE];    // 2 x 8704 B

    const int t    = threadIdx.x;
    const int lane = t & 31;
    const int wid  = t >> 5;
    const int g    = lane >> 2;     // 0..7
    const int tg   = lane & 3;      // 0..3
    const int bm   = blockIdx.x * 128;
    const int bn   = blockIdx.y * 128;
    const int wm   = (wid & 1) * 64;    // warp M offset in tile
    const int wn   = (wid >> 1) * 32;   // warp N offset in tile

    float acc[4][4][4];
#pragma unroll
    for (int mf = 0; mf < 4; mf++)
#pragma unroll
        for (int nf = 0; nf < 4; nf++)
#pragma unroll
            for (int r = 0; r < 4; r++) acc[mf][nf][r] = 0.0f;

    // per-thread gmem->smem mapping
    // A tile: 128 rows x 16 cols, 512 float4, 2 per thread
    // B tile: 16 rows x 128 cols, 512 float4, 2 per thread
    const int ra0 = t >> 2,          ca0 = (t & 3) * 4;
    const int ra1 = (t + 256) >> 2,  ca1 = ((t + 256) & 3) * 4;
    const int rb0 = t >> 5,          cb0 = (t & 31) * 4;
    const int rb1 = (t + 256) >> 5,  cb1 = ((t + 256) & 31) * 4;

    const int nkt = K >> 4;

    // ---- prologue: load tile 0 into buffer 0 ----
    {
        float4 a0 = *(const float4*)(A + (size_t)(bm + ra0) * K + ca0);
        float4 a1 = *(const float4*)(A + (size_t)(bm + ra1) * K + ca1);
        float4 b0 = *(const float4*)(W + (size_t)rb0 * N + bn + cb0);
        float4 b1 = *(const float4*)(W + (size_t)rb1 * N + bn + cb1);
        a0.x=tf32r(a0.x); a0.y=tf32r(a0.y); a0.z=tf32r(a0.z); a0.w=tf32r(a0.w);
        a1.x=tf32r(a1.x); a1.y=tf32r(a1.y); a1.z=tf32r(a1.z); a1.w=tf32r(a1.w);
        b0.x=tf32r(b0.x); b0.y=tf32r(b0.y); b0.z=tf32r(b0.z); b0.w=tf32r(b0.w);
        b1.x=tf32r(b1.x); b1.y=tf32r(b1.y); b1.z=tf32r(b1.z); b1.w=tf32r(b1.w);
        *(float4*)&As[0][ra0 * AS_STRIDE + ca0] = a0;
        *(float4*)&As[0][ra1 * AS_STRIDE + ca1] = a1;
        *(float4*)&Bs[0][rb0 * BS_STRIDE + cb0] = b0;
        *(float4*)&Bs[0][rb1 * BS_STRIDE + cb1] = b1;
    }
    __syncthreads();

    for (int kt = 0; kt < nkt; kt++) {
        const int cur = kt & 1;
        float4 pa0, pa1, pb0, pb1;
        const bool pf = (kt + 1 < nkt);
        if (pf) {
            const int k0 = (kt + 1) << 4;
            pa0 = *(const float4*)(A + (size_t)(bm + ra0) * K + k0 + ca0);
            pa1 = *(const float4*)(A + (size_t)(bm + ra1) * K + k0 + ca1);
            pb0 = *(const float4*)(W + (size_t)(k0 + rb0) * N + bn + cb0);
            pb1 = *(const float4*)(W + (size_t)(k0 + rb1) * N + bn + cb1);
        }

        const float* as = As[cur];
        const float* bs = Bs[cur];
#pragma unroll
        for (int ks = 0; ks < 16; ks += 8) {
            uint32_t af[4][4], bf[4][2];
#pragma unroll
            for (int mf = 0; mf < 4; mf++) {
                const int m0 = wm + mf * 16 + g;
                af[mf][0] = __float_as_uint(as[(m0    ) * AS_STRIDE + ks + tg    ]);
                af[mf][1] = __float_as_uint(as[(m0 + 8) * AS_STRIDE + ks + tg    ]);
                af[mf][2] = __float_as_uint(as[(m0    ) * AS_STRIDE + ks + tg + 4]);
                af[mf][3] = __float_as_uint(as[(m0 + 8) * AS_STRIDE + ks + tg + 4]);
            }
#pragma unroll
            for (int nf = 0; nf < 4; nf++) {
                const int n0 = wn + nf * 8 + g;
                bf[nf][0] = __float_as_uint(bs[(ks + tg    ) * BS_STRIDE + n0]);
                bf[nf][1] = __float_as_uint(bs[(ks + tg + 4) * BS_STRIDE + n0]);
            }
#pragma unroll
            for (int mf = 0; mf < 4; mf++)
#pragma unroll
                for (int nf = 0; nf < 4; nf++) {
                    asm volatile(
                        "mma.sync.aligned.m16n8k8.row.col.f32.tf32.tf32.f32 "
                        "{%0,%1,%2,%3}, {%4,%5,%6,%7}, {%8,%9}, {%0,%1,%2,%3};"
                        : "+f"(acc[mf][nf][0]), "+f"(acc[mf][nf][1]),
                          "+f"(acc[mf][nf][2]), "+f"(acc[mf][nf][3])
                        : "r"(af[mf][0]), "r"(af[mf][1]), "r"(af[mf][2]), "r"(af[mf][3]),
                          "r"(bf[nf][0]), "r"(bf[nf][1]));
                }
        }

        if (pf) {
            const int nxt = 1 - cur;
            pa0.x=tf32r(pa0.x); pa0.y=tf32r(pa0.y); pa0.z=tf32r(pa0.z); pa0.w=tf32r(pa0.w);
            pa1.x=tf32r(pa1.x); pa1.y=tf32r(pa1.y); pa1.z=tf32r(pa1.z); pa1.w=tf32r(pa1.w);
            pb0.x=tf32r(pb0.x); pb0.y=tf32r(pb0.y); pb0.z=tf32r(pb0.z); pb0.w=tf32r(pb0.w);
            pb1.x=tf32r(pb1.x); pb1.y=tf32r(pb1.y); pb1.z=tf32r(pb1.z); pb1.w=tf32r(pb1.w);
            *(float4*)&As[nxt][ra0 * AS_STRIDE + ca0] = pa0;
            *(float4*)&As[nxt][ra1 * AS_STRIDE + ca1] = pa1;
            *(float4*)&Bs[nxt][rb0 * BS_STRIDE + cb0] = pb0;
            *(float4*)&Bs[nxt][rb1 * BS_STRIDE + cb1] = pb1;
        }
        __syncthreads();
    }

    // ---- epilogue: bias + store ----
#pragma unroll
    for (int mf = 0; mf < 4; mf++) {
        const int r0 = bm + wm + mf * 16 + g;
        const int r1 = r0 + 8;
#pragma unroll
        for (int nf = 0; nf < 4; nf++) {
            const int col = bn + wn + nf * 8 + tg * 2;
            const float b0 = bias[col], b1 = bias[col + 1];
            float2 v0 = make_float2(acc[mf][nf][0] + b0, acc[mf][nf][1] + b1);
            float2 v1 = make_float2(acc[mf][nf][2] + b0, acc[mf][nf][3] + b1);
            *(float2*)(C + (size_t)r0 * N + col) = v0;
            *(float2*)(C + (size_t)r1 * N + col) = v1;
        }
    }
}

// ---------------- embedding + sinusoidal positional encoding ---------------
__global__ void embed_kernel(const int* __restrict__ tokens,
                             const float* __restrict__ emb,
                             float* __restrict__ x)
{
    int row = blockIdx.x;
    int pos = row & (SS - 1);
    int tok = tokens[row];
    const float* e = emb + (size_t)tok * DD;
    float* xr = x + (size_t)row * DD;
    const float c = -logf(10000.0f) / (float)DD;
    for (int d = threadIdx.x; d < DD; d += blockDim.x) {
        int i = d >> 1;
        float ang = (float)pos * expf((float)(2 * i) * c);
        float pe = (d & 1) ? cosf(ang) : sinf(ang);
        xr[d] = e[d] + pe;
    }
}

// ---------------- causal flash attention (fp32, per-head) ------------------
__global__ void __launch_bounds__(128)
attn_kernel(const float* __restrict__ Q, const float* __restrict__ K,
            const float* __restrict__ V, float* __restrict__ O)
{
    __shared__ float Ks[32][64];
    __shared__ float Vs[32][64];

    const int b = blockIdx.z;
    const int h = blockIdx.y;
    const int qi = blockIdx.x * 128 + threadIdx.x;
    const size_t base = (size_t)(b * SS) * DD + (size_t)h * HD;

    float q[64];
    {
        const float* qrow = Q + base + (size_t)qi * DD;
#pragma unroll
        for (int d = 0; d < 64; d += 4) {
            float4 v = *(const float4*)(qrow + d);
            q[d] = v.x; q[d+1] = v.y; q[d+2] = v.z; q[d+3] = v.w;
        }
    }

    float o[64];
#pragma unroll
    for (int d = 0; d < 64; d++) o[d] = 0.0f;
    float m = -1e30f, l = 0.0f;

    const int kend = blockIdx.x * 128 + 128;
    for (int kt = 0; kt < kend; kt += 32) {
#pragma unroll
        for (int i = 0; i < 4; i++) {
            int idx4 = threadIdx.x + i * 128;
            int r = idx4 >> 4;
            int c = (idx4 & 15) * 4;
            size_t gaddr = base + (size_t)(kt + r) * DD + c;
            *(float4*)&Ks[r][c] = *(const float4*)(K + gaddr);
            *(float4*)&Vs[r][c] = *(const float4*)(V + gaddr);
        }
        __syncthreads();

        int jmax = qi - kt + 1;
        if (jmax > 32) jmax = 32;
        for (int j = 0; j < jmax; j++) {
            float s = 0.0f;
#pragma unroll
            for (int d = 0; d < 64; d++) s += q[d] * Ks[j][d];
            s *= 0.125f;
            float nm = fmaxf(m, s);
            float corr = __expf(m - nm);
            float p = __expf(s - nm);
            l = l * corr + p;
#pragma unroll
            for (int d = 0; d < 64; d++)
                o[d] = o[d] * corr + p * Vs[j][d];
            m = nm;
        }
        __syncthreads();
    }

    float inv = 1.0f / l;
    float* orow = O + base + (size_t)qi * DD;
#pragma unroll
    for (int d = 0; d < 64; d += 4) {
        float4 v;
        v.x = o[d] * inv; v.y = o[d+1] * inv;
        v.z = o[d+2] * inv; v.w = o[d+3] * inv;
        *(float4*)(orow + d) = v;
    }
}

// ---------------- residual add + layernorm (in place on x) ----------------
__global__ void __launch_bounds__(256)
ln_res_kernel(float* __restrict__ x, const float* __restrict__ res,
              const float* __restrict__ g, const float* __restrict__ beta)
{
    __shared__ float red[256];
    const int row = blockIdx.x;
    const int tid = threadIdx.x;
    float* xr = x + (size_t)row * DD;
    const float* rr = res + (size_t)row * DD;

    float y[4];
    float s = 0.0f;
#pragma unroll
    for (int i = 0; i < 4; i++) {
        int d = tid + i * 256;
        y[i] = xr[d] + rr[d];
        s += y[i];
    }
    red[tid] = s; __syncthreads();
    for (int off = 128; off > 0; off >>= 1) {
        if (tid < off) red[tid] += red[tid + off];
        __syncthreads();
    }
    float mu = red[0] * (1.0f / (float)DD);
    __syncthreads();

    float vs = 0.0f;
#pragma unroll
    for (int i = 0; i < 4; i++) {
        float d2 = y[i] - mu;
        vs += d2 * d2;
    }
    red[tid] = vs; __syncthreads();
    for (int off = 128; off > 0; off >>= 1) {
        if (tid < off) red[tid] += red[tid + off];
        __syncthreads();
    }
    float var = red[0] * (1.0f / (float)DD);
    float inv = rsqrtf(var + 1e-5f);

#pragma unroll
    for (int i = 0; i < 4; i++) {
        int d = tid + i * 256;
        xr[d] = (y[i] - mu) * inv * g[d] + beta[d];
    }
}

// ---------------------------------------------------------------------------
extern "C" void kernel_launch(void* const* d_in, const int* in_sizes, int n_in,
                              void* d_out, int out_size)
{
    const int*   tokens = (const int*)  d_in[0];
    const float* emb    = (const float*)d_in[1];
    const float* qw     = (const float*)d_in[2];
    const float* qb     = (const float*)d_in[3];
    const float* kw     = (const float*)d_in[4];
    const float* kb     = (const float*)d_in[5];
    const float* vw     = (const float*)d_in[6];
    const float* vb     = (const float*)d_in[7];
    const float* ow     = (const float*)d_in[8];
    const float* ob     = (const float*)d_in[9];
    const float* ln_g   = (const float*)d_in[10];
    const float* ln_b   = (const float*)d_in[11];
    const float* out_w  = (const float*)d_in[12];
    const float* out_b  = (const float*)d_in[13];
    float* logits = (float*)d_out;

    float *x, *q, *k, *v, *ctx, *attn;
    cudaGetSymbolAddress((void**)&x,    g_x);
    cudaGetSymbolAddress((void**)&q,    g_q);
    cudaGetSymbolAddress((void**)&k,    g_k);
    cudaGetSymbolAddress((void**)&v,    g_v);
    cudaGetSymbolAddress((void**)&ctx,  g_ctx);
    cudaGetSymbolAddress((void**)&attn, g_attn);

    embed_kernel<<<NROW, 256>>>(tokens, emb, x);

    dim3 gproj(NROW / 128, DD / 128);     // (16, 8)
    dim3 gattn(SS / 128, HH, BB);

    for (int l = 0; l < LL; l++) {
        size_t wo = (size_t)l * DD * DD;
        size_t bo = (size_t)l * DD;
        gemm_mma<<<gproj, 256>>>(x,   qw + wo, qb + bo, q,    NROW, DD, DD);
        gemm_mma<<<gproj, 256>>>(x,   kw + wo, kb + bo, k,    NROW, DD, DD);
        gemm_mma<<<gproj, 256>>>(x,   vw + wo, vb + bo, v,    NROW, DD, DD);
        attn_kernel<<<gattn, 128>>>(q, k, v, ctx);
        gemm_mma<<<gproj, 256>>>(ctx, ow + wo, ob + bo, attn, NROW, DD, DD);
        ln_res_kernel<<<NROW, 256>>>(x, attn, ln_g + bo, ln_b + bo);
    }

    // final logits: [2048,1024] @ [1024,32000] + bias
    dim3 gout(NROW / 128, VV / 128);      // (16, 250)
    gemm_mma<<<gout, 256>>>(x, out_w, out_b, logits, NROW, VV, DD);
}

// round 4
// speedup vs baseline: 2.2832x; 1.2069x over previous
#include <cuda_runtime.h>
#include <cstdint>
#include <math.h>

#define BB 2
#define SS 1024
#define DD 1024
#define HH 16
#define HD 64
#define LL 4
#define VV 32000
#define NROW (BB * SS)   // 2048

// ---------------- scratch (static device globals; no allocs allowed) --------
__device__ float g_x[NROW * DD];
__device__ float g_q[NROW * DD];
__device__ float g_k[NROW * DD];
__device__ float g_v[NROW * DD];
__device__ float g_ctx[NROW * DD];
__device__ float g_attn[NROW * DD];

__device__ __forceinline__ float tf32r(float x) {
    float r; asm("cvt.rna.tf32.f32 %0, %1;" : "=f"(r) : "f"(x)); return r;
}

// =================== tf32 mma.sync GEMM core ================================
// C[M,N] = A[M,K] @ W[K,N] + bias[N]
// CTA tile 128x128, BK=16, 256 threads (8 warps), warp tile 64x32.
// As[m][k] stride 20, Bs[k][n] stride 136: conflict-free fragment reads.

#define AS_STRIDE 20
#define BS_STRIDE 136

__device__ __forceinline__ void gemm_core(
    const float* __restrict__ A, const float* __restrict__ W,
    const float* __restrict__ bias, float* __restrict__ C,
    int M, int N, int K, int bm, int bn,
    float (*As)[128 * AS_STRIDE], float (*Bs)[16 * BS_STRIDE])
{
    const int t    = threadIdx.x;
    const int lane = t & 31;
    const int wid  = t >> 5;
    const int g    = lane >> 2;
    const int tg   = lane & 3;
    const int wm   = (wid & 1) * 64;
    const int wn   = (wid >> 1) * 32;

    float acc[4][4][4];
#pragma unroll
    for (int mf = 0; mf < 4; mf++)
#pragma unroll
        for (int nf = 0; nf < 4; nf++)
#pragma unroll
            for (int r = 0; r < 4; r++) acc[mf][nf][r] = 0.0f;

    const int ra0 = t >> 2,          ca0 = (t & 3) * 4;
    const int ra1 = (t + 256) >> 2,  ca1 = ((t + 256) & 3) * 4;
    const int rb0 = t >> 5,          cb0 = (t & 31) * 4;
    const int rb1 = (t + 256) >> 5,  cb1 = ((t + 256) & 31) * 4;

    const int nkt = K >> 4;

    {
        float4 a0 = *(const float4*)(A + (size_t)(bm + ra0) * K + ca0);
        float4 a1 = *(const float4*)(A + (size_t)(bm + ra1) * K + ca1);
        float4 b0 = *(const float4*)(W + (size_t)rb0 * N + bn + cb0);
        float4 b1 = *(const float4*)(W + (size_t)rb1 * N + bn + cb1);
        a0.x=tf32r(a0.x); a0.y=tf32r(a0.y); a0.z=tf32r(a0.z); a0.w=tf32r(a0.w);
        a1.x=tf32r(a1.x); a1.y=tf32r(a1.y); a1.z=tf32r(a1.z); a1.w=tf32r(a1.w);
        b0.x=tf32r(b0.x); b0.y=tf32r(b0.y); b0.z=tf32r(b0.z); b0.w=tf32r(b0.w);
        b1.x=tf32r(b1.x); b1.y=tf32r(b1.y); b1.z=tf32r(b1.z); b1.w=tf32r(b1.w);
        *(float4*)&As[0][ra0 * AS_STRIDE + ca0] = a0;
        *(float4*)&As[0][ra1 * AS_STRIDE + ca1] = a1;
        *(float4*)&Bs[0][rb0 * BS_STRIDE + cb0] = b0;
        *(float4*)&Bs[0][rb1 * BS_STRIDE + cb1] = b1;
    }
    __syncthreads();

    for (int kt = 0; kt < nkt; kt++) {
        const int cur = kt & 1;
        float4 pa0, pa1, pb0, pb1;
        const bool pf = (kt + 1 < nkt);
        if (pf) {
            const int k0 = (kt + 1) << 4;
            pa0 = *(const float4*)(A + (size_t)(bm + ra0) * K + k0 + ca0);
            pa1 = *(const float4*)(A + (size_t)(bm + ra1) * K + k0 + ca1);
            pb0 = *(const float4*)(W + (size_t)(k0 + rb0) * N + bn + cb0);
            pb1 = *(const float4*)(W + (size_t)(k0 + rb1) * N + bn + cb1);
        }

        const float* as = As[cur];
        const float* bs = Bs[cur];
#pragma unroll
        for (int ks = 0; ks < 16; ks += 8) {
            uint32_t af[4][4], bf[4][2];
#pragma unroll
            for (int mf = 0; mf < 4; mf++) {
                const int m0 = wm + mf * 16 + g;
                af[mf][0] = __float_as_uint(as[(m0    ) * AS_STRIDE + ks + tg    ]);
                af[mf][1] = __float_as_uint(as[(m0 + 8) * AS_STRIDE + ks + tg    ]);
                af[mf][2] = __float_as_uint(as[(m0    ) * AS_STRIDE + ks + tg + 4]);
                af[mf][3] = __float_as_uint(as[(m0 + 8) * AS_STRIDE + ks + tg + 4]);
            }
#pragma unroll
            for (int nf = 0; nf < 4; nf++) {
                const int n0 = wn + nf * 8 + g;
                bf[nf][0] = __float_as_uint(bs[(ks + tg    ) * BS_STRIDE + n0]);
                bf[nf][1] = __float_as_uint(bs[(ks + tg + 4) * BS_STRIDE + n0]);
            }
#pragma unroll
            for (int mf = 0; mf < 4; mf++)
#pragma unroll
                for (int nf = 0; nf < 4; nf++) {
                    asm volatile(
                        "mma.sync.aligned.m16n8k8.row.col.f32.tf32.tf32.f32 "
                        "{%0,%1,%2,%3}, {%4,%5,%6,%7}, {%8,%9}, {%0,%1,%2,%3};"
                        : "+f"(acc[mf][nf][0]), "+f"(acc[mf][nf][1]),
                          "+f"(acc[mf][nf][2]), "+f"(acc[mf][nf][3])
                        : "r"(af[mf][0]), "r"(af[mf][1]), "r"(af[mf][2]), "r"(af[mf][3]),
                          "r"(bf[nf][0]), "r"(bf[nf][1]));
                }
        }

        if (pf) {
            const int nxt = 1 - cur;
            pa0.x=tf32r(pa0.x); pa0.y=tf32r(pa0.y); pa0.z=tf32r(pa0.z); pa0.w=tf32r(pa0.w);
            pa1.x=tf32r(pa1.x); pa1.y=tf32r(pa1.y); pa1.z=tf32r(pa1.z); pa1.w=tf32r(pa1.w);
            pb0.x=tf32r(pb0.x); pb0.y=tf32r(pb0.y); pb0.z=tf32r(pb0.z); pb0.w=tf32r(pb0.w);
            pb1.x=tf32r(pb1.x); pb1.y=tf32r(pb1.y); pb1.z=tf32r(pb1.z); pb1.w=tf32r(pb1.w);
            *(float4*)&As[nxt][ra0 * AS_STRIDE + ca0] = pa0;
            *(float4*)&As[nxt][ra1 * AS_STRIDE + ca1] = pa1;
            *(float4*)&Bs[nxt][rb0 * BS_STRIDE + cb0] = pb0;
            *(float4*)&Bs[nxt][rb1 * BS_STRIDE + cb1] = pb1;
        }
        __syncthreads();
    }

#pragma unroll
    for (int mf = 0; mf < 4; mf++) {
        const int r0 = bm + wm + mf * 16 + g;
        const int r1 = r0 + 8;
#pragma unroll
        for (int nf = 0; nf < 4; nf++) {
            const int col = bn + wn + nf * 8 + tg * 2;
            const float b0 = bias[col], b1 = bias[col + 1];
            float2 v0 = make_float2(acc[mf][nf][0] + b0, acc[mf][nf][1] + b1);
            float2 v1 = make_float2(acc[mf][nf][2] + b0, acc[mf][nf][3] + b1);
            *(float2*)(C + (size_t)r0 * N + col) = v0;
            *(float2*)(C + (size_t)r1 * N + col) = v1;
        }
    }
}

__global__ void __launch_bounds__(256, 2)
gemm_mma(const float* __restrict__ A, const float* __restrict__ W,
         const float* __restrict__ bias, float* __restrict__ C,
         int M, int N, int K)
{
    __shared__ float As[2][128 * AS_STRIDE];
    __shared__ float Bs[2][16 * BS_STRIDE];
    gemm_core(A, W, bias, C, M, N, K, blockIdx.x * 128, blockIdx.y * 128, As, Bs);
}

// fused QKV: grid.z in {0,1,2} selects the projection
__global__ void __launch_bounds__(256, 2)
gemm_mma_qkv(const float* __restrict__ A,
             const float* __restrict__ qw, const float* __restrict__ kw,
             const float* __restrict__ vw,
             const float* __restrict__ qb, const float* __restrict__ kb,
             const float* __restrict__ vb,
             float* __restrict__ qo, float* __restrict__ ko, float* __restrict__ vo)
{
    __shared__ float As[2][128 * AS_STRIDE];
    __shared__ float Bs[2][16 * BS_STRIDE];
    const float* W    = (blockIdx.z == 0) ? qw : (blockIdx.z == 1) ? kw : vw;
    const float* bias = (blockIdx.z == 0) ? qb : (blockIdx.z == 1) ? kb : vb;
    float*       C    = (blockIdx.z == 0) ? qo : (blockIdx.z == 1) ? ko : vo;
    gemm_core(A, W, bias, C, NROW, DD, DD, blockIdx.x * 128, blockIdx.y * 128, As, Bs);
}

// ---------------- embedding + sinusoidal positional encoding ---------------
__global__ void embed_kernel(const int* __restrict__ tokens,
                             const float* __restrict__ emb,
                             float* __restrict__ x)
{
    int row = blockIdx.x;
    int pos = row & (SS - 1);
    int tok = tokens[row];
    const float* e = emb + (size_t)tok * DD;
    float* xr = x + (size_t)row * DD;
    const float c = -logf(10000.0f) / (float)DD;
    for (int d = threadIdx.x; d < DD; d += blockDim.x) {
        int i = d >> 1;
        float ang = (float)pos * expf((float)(2 * i) * c);
        float pe = (d & 1) ? cosf(ang) : sinf(ang);
        xr[d] = e[d] + pe;
    }
}

// ---------------- causal flash attention, tile-level online softmax --------
// grid: (S/128, H, B); 128 threads; thread = one query row.
__global__ void __launch_bounds__(128)
attn_kernel(const float* __restrict__ Q, const float* __restrict__ K,
            const float* __restrict__ V, float* __restrict__ O)
{
    __shared__ float Ks[32][64];
    __shared__ float Vs[32][64];

    const int b = blockIdx.z;
    const int h = blockIdx.y;
    const int qi = blockIdx.x * 128 + threadIdx.x;
    const size_t base = (size_t)(b * SS) * DD + (size_t)h * HD;

    float q[64];
    {
        const float* qrow = Q + base + (size_t)qi * DD;
#pragma unroll
        for (int d = 0; d < 64; d += 4) {
            float4 v = *(const float4*)(qrow + d);
            q[d] = v.x; q[d+1] = v.y; q[d+2] = v.z; q[d+3] = v.w;
        }
    }

    float o[64];
#pragma unroll
    for (int d = 0; d < 64; d++) o[d] = 0.0f;
    float m = -1e30f, l = 0.0f;

    const int kend = blockIdx.x * 128 + 128;
    for (int kt = 0; kt < kend; kt += 32) {
#pragma unroll
        for (int i = 0; i < 4; i++) {
            int idx4 = threadIdx.x + i * 128;
            int r = idx4 >> 4;
            int c = (idx4 & 15) * 4;
            size_t gaddr = base + (size_t)(kt + r) * DD + c;
            *(float4*)&Ks[r][c] = *(const float4*)(K + gaddr);
            *(float4*)&Vs[r][c] = *(const float4*)(V + gaddr);
        }
        __syncthreads();

        const int jmax = qi - kt + 1;       // may be <=0 (fully masked) or >=32 (full)
        float sv[32];
        float tmax = -1e30f;
        // pass 1: all 32 scores (independent, pipelineable)
#pragma unroll
        for (int j = 0; j < 32; j++) {
            float s = 0.0f;
#pragma unroll
            for (int d = 0; d < 64; d++) s += q[d] * Ks[j][d];
            s *= 0.125f;
            sv[j] = (j < jmax) ? s : -1e30f;
            tmax = fmaxf(tmax, sv[j]);
        }
        // single rescale per tile
        float nm = fmaxf(m, tmax);
        float corr = __expf(m - nm);
        l *= corr;
#pragma unroll
        for (int d = 0; d < 64; d++) o[d] *= corr;
        // pass 2: accumulate
#pragma unroll
        for (int j = 0; j < 32; j++) {
            float p = __expf(sv[j] - nm);
            l += p;
#pragma unroll
            for (int d = 0; d < 64; d++)
                o[d] += p * Vs[j][d];
        }
        m = nm;
        __syncthreads();
    }

    float inv = 1.0f / l;
    float* orow = O + base + (size_t)qi * DD;
#pragma unroll
    for (int d = 0; d < 64; d += 4) {
        float4 v;
        v.x = o[d] * inv; v.y = o[d+1] * inv;
        v.z = o[d+2] * inv; v.w = o[d+3] * inv;
        *(float4*)(orow + d) = v;
    }
}

// ---------------- residual add + layernorm (in place on x) ----------------
__global__ void __launch_bounds__(256)
ln_res_kernel(float* __restrict__ x, const float* __restrict__ res,
              const float* __restrict__ g, const float* __restrict__ beta)
{
    __shared__ float red[256];
    const int row = blockIdx.x;
    const int tid = threadIdx.x;
    float* xr = x + (size_t)row * DD;
    const float* rr = res + (size_t)row * DD;

    float y[4];
    float s = 0.0f;
#pragma unroll
    for (int i = 0; i < 4; i++) {
        int d = tid + i * 256;
        y[i] = xr[d] + rr[d];
        s += y[i];
    }
    red[tid] = s; __syncthreads();
    for (int off = 128; off > 0; off >>= 1) {
        if (tid < off) red[tid] += red[tid + off];
        __syncthreads();
    }
    float mu = red[0] * (1.0f / (float)DD);
    __syncthreads();

    float vs = 0.0f;
#pragma unroll
    for (int i = 0; i < 4; i++) {
        float d2 = y[i] - mu;
        vs += d2 * d2;
    }
    red[tid] = vs; __syncthreads();
    for (int off = 128; off > 0; off >>= 1) {
        if (tid < off) red[tid] += red[tid + off];
        __syncthreads();
    }
    float var = red[0] * (1.0f / (float)DD);
    float inv = rsqrtf(var + 1e-5f);

#pragma unroll
    for (int i = 0; i < 4; i++) {
        int d = tid + i * 256;
        xr[d] = (y[i] - mu) * inv * g[d] + beta[d];
    }
}

// ---------------------------------------------------------------------------
extern "C" void kernel_launch(void* const* d_in, const int* in_sizes, int n_in,
                              void* d_out, int out_size)
{
    const int*   tokens = (const int*)  d_in[0];
    const float* emb    = (const float*)d_in[1];
    const float* qw     = (const float*)d_in[2];
    const float* qb     = (const float*)d_in[3];
    const float* kw     = (const float*)d_in[4];
    const float* kb     = (const float*)d_in[5];
    const float* vw     = (const float*)d_in[6];
    const float* vb     = (const float*)d_in[7];
    const float* ow     = (const float*)d_in[8];
    const float* ob     = (const float*)d_in[9];
    const float* ln_g   = (const float*)d_in[10];
    const float* ln_b   = (const float*)d_in[11];
    const float* out_w  = (const float*)d_in[12];
    const float* out_b  = (const float*)d_in[13];
    float* logits = (float*)d_out;

    float *x, *q, *k, *v, *ctx, *attn;
    cudaGetSymbolAddress((void**)&x,    g_x);
    cudaGetSymbolAddress((void**)&q,    g_q);
    cudaGetSymbolAddress((void**)&k,    g_k);
    cudaGetSymbolAddress((void**)&v,    g_v);
    cudaGetSymbolAddress((void**)&ctx,  g_ctx);
    cudaGetSymbolAddress((void**)&attn, g_attn);

    embed_kernel<<<NROW, 256>>>(tokens, emb, x);

    dim3 gqkv(NROW / 128, DD / 128, 3);   // (16, 8, 3)
    dim3 gproj(NROW / 128, DD / 128);     // (16, 8)
    dim3 gattn(SS / 128, HH, BB);

    for (int l = 0; l < LL; l++) {
        size_t wo = (size_t)l * DD * DD;
        size_t bo = (size_t)l * DD;
        gemm_mma_qkv<<<gqkv, 256>>>(x, qw + wo, kw + wo, vw + wo,
                                    qb + bo, kb + bo, vb + bo, q, k, v);
        attn_kernel<<<gattn, 128>>>(q, k, v, ctx);
        gemm_mma<<<gproj, 256>>>(ctx, ow + wo, ob + bo, attn, NROW, DD, DD);
        ln_res_kernel<<<NROW, 256>>>(x, attn, ln_g + bo, ln_b + bo);
    }

    // final logits: [2048,1024] @ [1024,32000] + bias
    dim3 gout(NROW / 128, VV / 128);      // (16, 250)
    gemm_mma<<<gout, 256>>>(x, out_w, out_b, logits, NROW, VV, DD);
}